// round 11
// baseline (speedup 1.0000x reference)
#include <cuda_runtime.h>
#include <cuda_fp16.h>

// GatheringLoss — R11: 3 CTAs/SM. BM=64, 256 thr, regs forced <=85 via
// __launch_bounds__(256,3), smem 52KB (A 17KB + 2x17KB B double-buffer of
// 64-key chunks). Warp tile 16 rows x 32 keys, fp16 HMMA.
// per-row 4 approx candidates -> exact fp32 rescore -> losses.
// out = [kg (65536) | vg (65536)]

#define T_TOTAL 65536
#define M_KEYS  1024
#define C_DIM   128
#define BM      64
#define THREADS 256
#define SAB     272                 // smem row stride (bytes)

#define OFF_A     0                 // 64 rows * 272B = 17408
#define OFF_B(buf) (17408 + (buf) * 17408)   // 64 keys * 272B per buffer
#define SM_TOTAL  52224

__device__ __half g_keys_h[M_KEYS * C_DIM];

__device__ __forceinline__ unsigned smem_u32(const void* p) {
    unsigned a;
    asm("{ .reg .u64 t; cvta.to.shared.u64 t, %1; cvt.u32.u64 %0, t; }" : "=r"(a) : "l"(p));
    return a;
}

#define LDSM_X4(r0, r1, r2, r3, a)                                             \
    asm volatile("ldmatrix.sync.aligned.m8n8.x4.shared.b16 {%0,%1,%2,%3}, [%4];" \
                 : "=r"(r0), "=r"(r1), "=r"(r2), "=r"(r3) : "r"(a))

__device__ __forceinline__ void mma_f16(float* d, const unsigned* a,
                                        unsigned b0, unsigned b1) {
    asm("mma.sync.aligned.m16n8k16.row.col.f32.f16.f16.f32 "
        "{%0,%1,%2,%3}, {%4,%5,%6,%7}, {%8,%9}, {%0,%1,%2,%3};"
        : "+f"(d[0]), "+f"(d[1]), "+f"(d[2]), "+f"(d[3])
        : "r"(a[0]), "r"(a[1]), "r"(a[2]), "r"(a[3]), "r"(b0), "r"(b1));
}

#define CP16(dst, src) \
    asm volatile("cp.async.cg.shared.global [%0], [%1], 16;" :: "r"(dst), "l"(src))
#define CP_COMMIT() asm volatile("cp.async.commit_group;" ::: "memory")
#define CP_WAIT1()  asm volatile("cp.async.wait_group 1;"  ::: "memory")
#define CP_WAIT0()  asm volatile("cp.async.wait_group 0;"  ::: "memory")

#define UPD(s1, i1, s2, i2, v, n)                          \
    do { if ((v) > (s1)) { s2 = s1; i2 = i1; s1 = (v); i1 = (n); } \
         else if ((v) > (s2)) { s2 = (v); i2 = (n); } } while (0)

__device__ __forceinline__ void merge2(float& s1, int& i1, float& s2, int& i2,
                                       float t1, int j1, float t2, int j2) {
    if (t1 > s1 || (t1 == s1 && j1 < i1)) {
        float ns2; int ni2;
        if (s1 > t2 || (s1 == t2 && i1 < j2)) { ns2 = s1; ni2 = i1; }
        else                                  { ns2 = t2; ni2 = j2; }
        s1 = t1; i1 = j1; s2 = ns2; i2 = ni2;
    } else if (t1 > s2 || (t1 == s2 && j1 < i2)) {
        s2 = t1; i2 = j1;
    }
}

__global__ void prep_keys_kernel(const float* __restrict__ keys) {
    int i = blockIdx.x * blockDim.x + threadIdx.x;
    if (i < M_KEYS * C_DIM) g_keys_h[i] = __float2half_rn(keys[i]);
}

__global__ __launch_bounds__(THREADS, 3)
void gathering_loss_kernel(const float* __restrict__ q,
                           const float* __restrict__ r,
                           const float* __restrict__ keys,
                           const float* __restrict__ values,
                           float* __restrict__ out)
{
    extern __shared__ char smem[];
    const unsigned sb = smem_u32(smem);
    const int tid  = threadIdx.x;
    const int lane = tid & 31;
    const int wid  = tid >> 5;          // 0..7
    const int rowg = (wid & 3) * 16;    // warp's 16-row group within 64
    const int half = wid >> 2;          // warp's 32-key half of each 64-key chunk
    const int row0 = blockIdx.x * BM;

    // ---- A tile: q rows -> fp16 smem [m][k], stride 272B ----
    {
        const float4* q4 = (const float4*)(q + (size_t)row0 * C_DIM);
        #pragma unroll
        for (int it = 0; it < (BM * C_DIM / 4) / THREADS; ++it) {
            int i = tid + it * THREADS;
            int m  = i >> 5;
            int k4 = (i & 31) << 2;
            float4 v = q4[i];
            __half2 h01 = __floats2half2_rn(v.x, v.y);
            __half2 h23 = __floats2half2_rn(v.z, v.w);
            char* p = smem + OFF_A + m * SAB + k4 * 2;
            *(__half2*)(p)     = h01;
            *(__half2*)(p + 4) = h23;
        }
    }

    auto load_b = [&](int chunk, int buf) {   // 64 keys = 16 KB
        const char* src = (const char*)(g_keys_h + (size_t)chunk * 64 * C_DIM);
        unsigned dst = sb + OFF_B(buf);
        #pragma unroll
        for (int it = 0; it < 4; ++it) {
            int s  = tid + it * THREADS;      // 1024 16B segments
            int n  = s >> 4;
            int ks = s & 15;
            CP16(dst + n * SAB + ks * 16, src + n * 256 + ks * 16);
        }
    };
    load_b(0, 0);
    CP_COMMIT();
    __syncthreads();

    // ---- persistent A fragments (32 regs) ----
    unsigned ahi[8][4];
    {
        int amat = lane >> 3;
        unsigned apart = sb + OFF_A
                       + (unsigned)(rowg + (lane & 7) + ((amat & 1) << 3)) * SAB
                       + ((amat >> 1) << 4);
        #pragma unroll
        for (int ks = 0; ks < 8; ++ks)
            LDSM_X4(ahi[ks][0], ahi[ks][1], ahi[ks][2], ahi[ks][3], apart + ks * 32);
    }

    // B ldmatrix: x4 loads two adjacent n8 tiles (mats 0,1 -> nt even; 2,3 -> odd)
    const int bmat = lane >> 3;
    const unsigned bpart = (unsigned)((lane & 7) + ((bmat >> 1) << 3)) * SAB
                         + ((bmat & 1) << 4)
                         + (unsigned)(half * 32) * SAB;

    float s1a = -3.402823466e38f, s2a = -3.402823466e38f;
    float s1b = -3.402823466e38f, s2b = -3.402823466e38f;
    int i1a = 0, i2a = 0, i1b = 0, i2b = 0;

    #pragma unroll 1
    for (int c = 0; c < 16; ++c) {
        if (c < 15) { load_b(c + 1, (c + 1) & 1); CP_COMMIT(); CP_WAIT1(); }
        else        { CP_WAIT0(); }
        __syncthreads();

        const unsigned bbuf = sb + OFF_B(c & 1) + bpart;

        float acc[4][4];
        #pragma unroll
        for (int nt = 0; nt < 4; ++nt)
            #pragma unroll
            for (int x = 0; x < 4; ++x) acc[nt][x] = 0.f;

        #pragma unroll
        for (int ks = 0; ks < 8; ++ks) {
            #pragma unroll
            for (int p = 0; p < 2; ++p) {      // pair p covers nt=2p, 2p+1
                unsigned b0, b1, b2, b3;
                LDSM_X4(b0, b1, b2, b3, bbuf + (unsigned)(p * 16) * SAB + ks * 32);
                mma_f16(acc[2 * p],     ahi[ks], b0, b1);
                mma_f16(acc[2 * p + 1], ahi[ks], b2, b3);
            }
        }

        const int colbase = c * 64 + half * 32 + (lane & 3) * 2;
        #pragma unroll
        for (int nt = 0; nt < 4; ++nt) {
            int nb = colbase + nt * 8;
            UPD(s1a, i1a, s2a, i2a, acc[nt][0], nb);
            UPD(s1a, i1a, s2a, i2a, acc[nt][1], nb + 1);
            UPD(s1b, i1b, s2b, i2b, acc[nt][2], nb);
            UPD(s1b, i1b, s2b, i2b, acc[nt][3], nb + 1);
        }
        __syncthreads();
    }

    // ---- quad merge -> (row, half) top-2 ----
    #pragma unroll
    for (int off = 1; off <= 2; off <<= 1) {
        float t1 = __shfl_xor_sync(0xffffffffu, s1a, off);
        int   j1 = __shfl_xor_sync(0xffffffffu, i1a, off);
        float t2 = __shfl_xor_sync(0xffffffffu, s2a, off);
        int   j2 = __shfl_xor_sync(0xffffffffu, i2a, off);
        merge2(s1a, i1a, s2a, i2a, t1, j1, t2, j2);
        t1 = __shfl_xor_sync(0xffffffffu, s1b, off);
        j1 = __shfl_xor_sync(0xffffffffu, i1b, off);
        t2 = __shfl_xor_sync(0xffffffffu, s2b, off);
        j2 = __shfl_xor_sync(0xffffffffu, i2b, off);
        merge2(s1b, i1b, s2b, i2b, t1, j1, t2, j2);
    }

    int* cand = (int*)smem;          // [64][4] = 1KB, reuses A region
    if ((lane & 3) == 0) {
        int ra = rowg + (lane >> 2);
        cand[ra * 4 + half * 2 + 0]       = i1a;
        cand[ra * 4 + half * 2 + 1]       = i2a;
        cand[(ra + 8) * 4 + half * 2 + 0] = i1b;
        cand[(ra + 8) * 4 + half * 2 + 1] = i2b;
    }
    __syncthreads();

    // ---- epilogue: 4 threads/row; exact fp32 rescore of 4 candidates + losses ----
    {
        int row = tid >> 2;              // 0..63
        int sub = tid & 3;
        int grow = row0 + row;
        int4 cd = *(const int4*)&cand[row * 4];
        int cidx[4] = {cd.x, cd.y, cd.z, cd.w};

        const float4* qp = (const float4*)(q + (size_t)grow * C_DIM + sub * 32);
        float4 qv[8];
        #pragma unroll
        for (int i = 0; i < 8; ++i) qv[i] = qp[i];

        float dots[4];
        #pragma unroll
        for (int j = 0; j < 4; ++j) {
            const float4* kp = (const float4*)(keys + (size_t)cidx[j] * C_DIM + sub * 32);
            float s = 0.f;
            #pragma unroll
            for (int i = 0; i < 8; ++i) {
                float4 a = qv[i], b = kp[i];
                s = fmaf(a.x, b.x, s); s = fmaf(a.y, b.y, s);
                s = fmaf(a.z, b.z, s); s = fmaf(a.w, b.w, s);
            }
            dots[j] = s;
        }
        #pragma unroll
        for (int off = 1; off <= 2; off <<= 1)
            #pragma unroll
            for (int j = 0; j < 4; ++j)
                dots[j] += __shfl_xor_sync(0xffffffffu, dots[j], off);

        int   bi = cidx[0];
        float bs = dots[0];
        #pragma unroll
        for (int j = 1; j < 4; ++j)
            if (dots[j] > bs || (dots[j] == bs && cidx[j] < bi)) { bs = dots[j]; bi = cidx[j]; }

        const float4* kp = (const float4*)(keys   + (size_t)bi   * C_DIM + sub * 32);
        const float4* rp = (const float4*)(r      + (size_t)grow * C_DIM + sub * 32);
        const float4* vp = (const float4*)(values + (size_t)bi   * C_DIM + sub * 32);
        float sk = 0.f, sv = 0.f;
        #pragma unroll
        for (int i = 0; i < 8; ++i) {
            float4 a = qv[i], b = kp[i];
            float d;
            d = a.x - b.x; sk = fmaf(d, d, sk);
            d = a.y - b.y; sk = fmaf(d, d, sk);
            d = a.z - b.z; sk = fmaf(d, d, sk);
            d = a.w - b.w; sk = fmaf(d, d, sk);
            float4 e = rp[i], f = vp[i];
            d = e.x - f.x; sv = fmaf(d, d, sv);
            d = e.y - f.y; sv = fmaf(d, d, sv);
            d = e.z - f.z; sv = fmaf(d, d, sv);
            d = e.w - f.w; sv = fmaf(d, d, sv);
        }
        #pragma unroll
        for (int off = 1; off <= 2; off <<= 1) {
            sk += __shfl_xor_sync(0xffffffffu, sk, off);
            sv += __shfl_xor_sync(0xffffffffu, sv, off);
        }
        if (sub == 0) out[grow]           = sk;
        if (sub == 1) out[T_TOTAL + grow] = sv;
    }
}

extern "C" void kernel_launch(void* const* d_in, const int* in_sizes, int n_in,
                              void* d_out, int out_size)
{
    const float* q      = (const float*)d_in[0];
    const float* r      = (const float*)d_in[1];
    const float* keys   = (const float*)d_in[2];
    const float* values = (const float*)d_in[3];
    float* out = (float*)d_out;

    prep_keys_kernel<<<(M_KEYS * C_DIM + 255) / 256, 256>>>(keys);

    cudaFuncSetAttribute(gathering_loss_kernel,
                         cudaFuncAttributeMaxDynamicSharedMemorySize, SM_TOTAL);
    gathering_loss_kernel<<<T_TOTAL / BM, THREADS, SM_TOTAL>>>(q, r, keys, values, out);
}

// round 12
// speedup vs baseline: 1.0361x; 1.0361x over previous
#include <cuda_runtime.h>
#include <cuda_fp16.h>

// GatheringLoss — R12: R10 layout (BM=64, 256thr, 2 CTAs/SM, 128-key chunks)
// + guarded top-2 updates (skip FSETP chains when chunk pair can't beat s2)
// + epilogue rescoring only the global approx top-2 candidates.
// out = [kg (65536) | vg (65536)]

#define T_TOTAL 65536
#define M_KEYS  1024
#define C_DIM   128
#define BM      64
#define THREADS 256
#define SAB     272                 // smem row stride (bytes)

#define OFF_A     0                 // 64 rows * 272B = 17408
#define OFF_B(buf) (17408 + (buf) * 34816)   // 128 keys * 272B per buffer
#define SM_TOTAL  87040

__device__ __half g_keys_h[M_KEYS * C_DIM];

__device__ __forceinline__ unsigned smem_u32(const void* p) {
    unsigned a;
    asm("{ .reg .u64 t; cvta.to.shared.u64 t, %1; cvt.u32.u64 %0, t; }" : "=r"(a) : "l"(p));
    return a;
}

#define LDSM_X4(r0, r1, r2, r3, a)                                             \
    asm volatile("ldmatrix.sync.aligned.m8n8.x4.shared.b16 {%0,%1,%2,%3}, [%4];" \
                 : "=r"(r0), "=r"(r1), "=r"(r2), "=r"(r3) : "r"(a))

__device__ __forceinline__ void mma_f16(float* d, const unsigned* a,
                                        unsigned b0, unsigned b1) {
    asm("mma.sync.aligned.m16n8k16.row.col.f32.f16.f16.f32 "
        "{%0,%1,%2,%3}, {%4,%5,%6,%7}, {%8,%9}, {%0,%1,%2,%3};"
        : "+f"(d[0]), "+f"(d[1]), "+f"(d[2]), "+f"(d[3])
        : "r"(a[0]), "r"(a[1]), "r"(a[2]), "r"(a[3]), "r"(b0), "r"(b1));
}

#define CP16(dst, src) \
    asm volatile("cp.async.cg.shared.global [%0], [%1], 16;" :: "r"(dst), "l"(src))
#define CP_COMMIT() asm volatile("cp.async.commit_group;" ::: "memory")
#define CP_WAIT1()  asm volatile("cp.async.wait_group 1;"  ::: "memory")
#define CP_WAIT0()  asm volatile("cp.async.wait_group 0;"  ::: "memory")

#define UPD(s1, i1, s2, i2, v, n)                          \
    do { if ((v) > (s1)) { s2 = s1; i2 = i1; s1 = (v); i1 = (n); } \
         else if ((v) > (s2)) { s2 = (v); i2 = (n); } } while (0)

__device__ __forceinline__ void merge2(float& s1, int& i1, float& s2, int& i2,
                                       float t1, int j1, float t2, int j2) {
    if (t1 > s1 || (t1 == s1 && j1 < i1)) {
        float ns2; int ni2;
        if (s1 > t2 || (s1 == t2 && i1 < j2)) { ns2 = s1; ni2 = i1; }
        else                                  { ns2 = t2; ni2 = j2; }
        s1 = t1; i1 = j1; s2 = ns2; i2 = ni2;
    } else if (t1 > s2 || (t1 == s2 && j1 < i2)) {
        s2 = t1; i2 = j1;
    }
}

__global__ void prep_keys_kernel(const float* __restrict__ keys) {
    int i = blockIdx.x * blockDim.x + threadIdx.x;
    if (i < M_KEYS * C_DIM) g_keys_h[i] = __float2half_rn(keys[i]);
}

__global__ __launch_bounds__(THREADS, 2)
void gathering_loss_kernel(const float* __restrict__ q,
                           const float* __restrict__ r,
                           const float* __restrict__ keys,
                           const float* __restrict__ values,
                           float* __restrict__ out)
{
    extern __shared__ char smem[];
    const unsigned sb = smem_u32(smem);
    const int tid  = threadIdx.x;
    const int lane = tid & 31;
    const int wid  = tid >> 5;          // 0..7
    const int rowg = (wid & 3) * 16;    // warp's 16-row group within 64
    const int half = wid >> 2;          // warp's 64-key half of each 128-key chunk
    const int row0 = blockIdx.x * BM;

    // ---- A tile: q rows -> fp16 smem [m][k], stride 272B ----
    {
        const float4* q4 = (const float4*)(q + (size_t)row0 * C_DIM);
        #pragma unroll
        for (int it = 0; it < (BM * C_DIM / 4) / THREADS; ++it) {
            int i = tid + it * THREADS;
            int m  = i >> 5;
            int k4 = (i & 31) << 2;
            float4 v = q4[i];
            __half2 h01 = __floats2half2_rn(v.x, v.y);
            __half2 h23 = __floats2half2_rn(v.z, v.w);
            char* p = smem + OFF_A + m * SAB + k4 * 2;
            *(__half2*)(p)     = h01;
            *(__half2*)(p + 4) = h23;
        }
    }

    auto load_b = [&](int chunk, int buf) {   // 128 keys = 32 KB
        const char* src = (const char*)(g_keys_h + (size_t)chunk * 128 * C_DIM);
        unsigned dst = sb + OFF_B(buf);
        #pragma unroll
        for (int it = 0; it < 8; ++it) {
            int s  = tid + it * THREADS;      // 2048 16B segments
            int n  = s >> 4;
            int ks = s & 15;
            CP16(dst + n * SAB + ks * 16, src + n * 256 + ks * 16);
        }
    };
    load_b(0, 0);
    CP_COMMIT();
    __syncthreads();

    // ---- persistent A fragments (32 regs) ----
    unsigned ahi[8][4];
    {
        int amat = lane >> 3;
        unsigned apart = sb + OFF_A
                       + (unsigned)(rowg + (lane & 7) + ((amat & 1) << 3)) * SAB
                       + ((amat >> 1) << 4);
        #pragma unroll
        for (int ks = 0; ks < 8; ++ks)
            LDSM_X4(ahi[ks][0], ahi[ks][1], ahi[ks][2], ahi[ks][3], apart + ks * 32);
    }

    const int bmat = lane >> 3;
    const unsigned bpart = (unsigned)((lane & 7) + ((bmat >> 1) << 3)) * SAB
                         + ((bmat & 1) << 4)
                         + (unsigned)(half * 64) * SAB;

    float s1a = -3.402823466e38f, s2a = -3.402823466e38f;
    float s1b = -3.402823466e38f, s2b = -3.402823466e38f;
    int i1a = 0, i2a = 0, i1b = 0, i2b = 0;

    #pragma unroll 1
    for (int c = 0; c < 8; ++c) {
        if (c < 7) { load_b(c + 1, (c + 1) & 1); CP_COMMIT(); CP_WAIT1(); }
        else       { CP_WAIT0(); }
        __syncthreads();

        const unsigned bbuf = sb + OFF_B(c & 1) + bpart;

        float acc[8][4];
        #pragma unroll
        for (int nt = 0; nt < 8; ++nt)
            #pragma unroll
            for (int x = 0; x < 4; ++x) acc[nt][x] = 0.f;

        #pragma unroll
        for (int ks = 0; ks < 8; ++ks) {
            #pragma unroll
            for (int p = 0; p < 4; ++p) {      // pair p covers nt=2p, 2p+1
                unsigned b0, b1, b2, b3;
                LDSM_X4(b0, b1, b2, b3, bbuf + (unsigned)(p * 16) * SAB + ks * 32);
                mma_f16(acc[2 * p],     ahi[ks], b0, b1);
                mma_f16(acc[2 * p + 1], ahi[ks], b2, b3);
            }
        }

        // guarded top-2 update: only run compare chain when it can change state
        const int colbase = c * 128 + half * 64 + (lane & 3) * 2;
        #pragma unroll
        for (int nt = 0; nt < 8; ++nt) {
            int nb = colbase + nt * 8;
            float mxa = fmaxf(acc[nt][0], acc[nt][1]);
            if (mxa > s2a) {
                UPD(s1a, i1a, s2a, i2a, acc[nt][0], nb);
                UPD(s1a, i1a, s2a, i2a, acc[nt][1], nb + 1);
            }
            float mxb = fmaxf(acc[nt][2], acc[nt][3]);
            if (mxb > s2b) {
                UPD(s1b, i1b, s2b, i2b, acc[nt][2], nb);
                UPD(s1b, i1b, s2b, i2b, acc[nt][3], nb + 1);
            }
        }
        __syncthreads();
    }

    // ---- quad merge -> (row, half) top-2 ----
    #pragma unroll
    for (int off = 1; off <= 2; off <<= 1) {
        float t1 = __shfl_xor_sync(0xffffffffu, s1a, off);
        int   j1 = __shfl_xor_sync(0xffffffffu, i1a, off);
        float t2 = __shfl_xor_sync(0xffffffffu, s2a, off);
        int   j2 = __shfl_xor_sync(0xffffffffu, i2a, off);
        merge2(s1a, i1a, s2a, i2a, t1, j1, t2, j2);
        t1 = __shfl_xor_sync(0xffffffffu, s1b, off);
        j1 = __shfl_xor_sync(0xffffffffu, i1b, off);
        t2 = __shfl_xor_sync(0xffffffffu, s2b, off);
        j2 = __shfl_xor_sync(0xffffffffu, i2b, off);
        merge2(s1b, i1b, s2b, i2b, t1, j1, t2, j2);
    }

    // cand smem: approx (score, idx) 4 per row — float[64][4] then int[64][4]
    float* cs = (float*)smem;
    int*   ci = (int*)(smem + 1024);
    if ((lane & 3) == 0) {
        int ra = rowg + (lane >> 2);
        cs[ra * 4 + half * 2 + 0] = s1a;  ci[ra * 4 + half * 2 + 0] = i1a;
        cs[ra * 4 + half * 2 + 1] = s2a;  ci[ra * 4 + half * 2 + 1] = i2a;
        cs[(ra + 8) * 4 + half * 2 + 0] = s1b;  ci[(ra + 8) * 4 + half * 2 + 0] = i1b;
        cs[(ra + 8) * 4 + half * 2 + 1] = s2b;  ci[(ra + 8) * 4 + half * 2 + 1] = i2b;
    }
    __syncthreads();

    // ---- epilogue: 4 threads/row; global approx top-2 -> exact rescore -> losses ----
    {
        int row = tid >> 2;              // 0..63
        int sub = tid & 3;
        int grow = row0 + row;
        float4 sc4 = *(const float4*)&cs[row * 4];
        int4   id4 = *(const int4*)&ci[row * 4];
        float sc[4] = {sc4.x, sc4.y, sc4.z, sc4.w};
        int   id[4] = {id4.x, id4.y, id4.z, id4.w};

        // approx top-1 and top-2 (first-index preference on ties)
        int b0 = 0;
        #pragma unroll
        for (int j = 1; j < 4; ++j)
            if (sc[j] > sc[b0] || (sc[j] == sc[b0] && id[j] < id[b0])) b0 = j;
        int b1 = (b0 == 0) ? 1 : 0;
        #pragma unroll
        for (int j = 0; j < 4; ++j)
            if (j != b0 && (sc[j] > sc[b1] || (sc[j] == sc[b1] && id[j] < id[b1]))) b1 = j;
        int c1 = id[b0], c2 = id[b1];

        const float4* qp = (const float4*)(q + (size_t)grow * C_DIM + sub * 32);
        float4 qv[8];
        #pragma unroll
        for (int i = 0; i < 8; ++i) qv[i] = qp[i];

        const float4* ka = (const float4*)(keys + (size_t)c1 * C_DIM + sub * 32);
        const float4* kb = (const float4*)(keys + (size_t)c2 * C_DIM + sub * 32);
        float sa = 0.f, sc2 = 0.f;
        #pragma unroll
        for (int i = 0; i < 8; ++i) {
            float4 a = qv[i], x = ka[i], y = kb[i];
            sa  = fmaf(a.x, x.x, sa);  sa  = fmaf(a.y, x.y, sa);
            sa  = fmaf(a.z, x.z, sa);  sa  = fmaf(a.w, x.w, sa);
            sc2 = fmaf(a.x, y.x, sc2); sc2 = fmaf(a.y, y.y, sc2);
            sc2 = fmaf(a.z, y.z, sc2); sc2 = fmaf(a.w, y.w, sc2);
        }
        #pragma unroll
        for (int off = 1; off <= 2; off <<= 1) {
            sa  += __shfl_xor_sync(0xffffffffu, sa,  off);
            sc2 += __shfl_xor_sync(0xffffffffu, sc2, off);
        }
        int bi = (sc2 > sa || (sc2 == sa && c2 < c1)) ? c2 : c1;

        const float4* kp = (const float4*)(keys   + (size_t)bi   * C_DIM + sub * 32);
        const float4* rp = (const float4*)(r      + (size_t)grow * C_DIM + sub * 32);
        const float4* vp = (const float4*)(values + (size_t)bi   * C_DIM + sub * 32);
        float sk = 0.f, sv = 0.f;
        #pragma unroll
        for (int i = 0; i < 8; ++i) {
            float4 a = qv[i], b = kp[i];
            float d;
            d = a.x - b.x; sk = fmaf(d, d, sk);
            d = a.y - b.y; sk = fmaf(d, d, sk);
            d = a.z - b.z; sk = fmaf(d, d, sk);
            d = a.w - b.w; sk = fmaf(d, d, sk);
            float4 e = rp[i], f = vp[i];
            d = e.x - f.x; sv = fmaf(d, d, sv);
            d = e.y - f.y; sv = fmaf(d, d, sv);
            d = e.z - f.z; sv = fmaf(d, d, sv);
            d = e.w - f.w; sv = fmaf(d, d, sv);
        }
        #pragma unroll
        for (int off = 1; off <= 2; off <<= 1) {
            sk += __shfl_xor_sync(0xffffffffu, sk, off);
            sv += __shfl_xor_sync(0xffffffffu, sv, off);
        }
        if (sub == 0) out[grow]           = sk;
        if (sub == 1) out[T_TOTAL + grow] = sv;
    }
}

extern "C" void kernel_launch(void* const* d_in, const int* in_sizes, int n_in,
                              void* d_out, int out_size)
{
    const float* q      = (const float*)d_in[0];
    const float* r      = (const float*)d_in[1];
    const float* keys   = (const float*)d_in[2];
    const float* values = (const float*)d_in[3];
    float* out = (float*)d_out;

    prep_keys_kernel<<<(M_KEYS * C_DIM + 255) / 256, 256>>>(keys);

    cudaFuncSetAttribute(gathering_loss_kernel,
                         cudaFuncAttributeMaxDynamicSharedMemorySize, SM_TOTAL);
    gathering_loss_kernel<<<T_TOTAL / BM, THREADS, SM_TOTAL>>>(q, r, keys, values, out);
}

// round 13
// speedup vs baseline: 1.0511x; 1.0145x over previous
#include <cuda_runtime.h>
#include <cuda_fp16.h>

// GatheringLoss — R13: R12 + single barrier per chunk (prefetch moved after the
// barrier; one barrier proves both data-ready and WAR-safety) + CTA chunk-phase
// rotation (odd CTAs start at chunk 4) to de-phase-lock co-resident CTAs.
// out = [kg (65536) | vg (65536)]

#define T_TOTAL 65536
#define M_KEYS  1024
#define C_DIM   128
#define BM      64
#define THREADS 256
#define SAB     272                 // smem row stride (bytes)

#define OFF_A     0                 // 64 rows * 272B = 17408
#define OFF_B(buf) (17408 + (buf) * 34816)   // 128 keys * 272B per buffer
#define SM_TOTAL  87040

__device__ __half g_keys_h[M_KEYS * C_DIM];

__device__ __forceinline__ unsigned smem_u32(const void* p) {
    unsigned a;
    asm("{ .reg .u64 t; cvta.to.shared.u64 t, %1; cvt.u32.u64 %0, t; }" : "=r"(a) : "l"(p));
    return a;
}

#define LDSM_X4(r0, r1, r2, r3, a)                                             \
    asm volatile("ldmatrix.sync.aligned.m8n8.x4.shared.b16 {%0,%1,%2,%3}, [%4];" \
                 : "=r"(r0), "=r"(r1), "=r"(r2), "=r"(r3) : "r"(a))

__device__ __forceinline__ void mma_f16(float* d, const unsigned* a,
                                        unsigned b0, unsigned b1) {
    asm("mma.sync.aligned.m16n8k16.row.col.f32.f16.f16.f32 "
        "{%0,%1,%2,%3}, {%4,%5,%6,%7}, {%8,%9}, {%0,%1,%2,%3};"
        : "+f"(d[0]), "+f"(d[1]), "+f"(d[2]), "+f"(d[3])
        : "r"(a[0]), "r"(a[1]), "r"(a[2]), "r"(a[3]), "r"(b0), "r"(b1));
}

#define CP16(dst, src) \
    asm volatile("cp.async.cg.shared.global [%0], [%1], 16;" :: "r"(dst), "l"(src))
#define CP_COMMIT() asm volatile("cp.async.commit_group;" ::: "memory")
#define CP_WAIT0()  asm volatile("cp.async.wait_group 0;"  ::: "memory")

#define UPD(s1, i1, s2, i2, v, n)                          \
    do { if ((v) > (s1)) { s2 = s1; i2 = i1; s1 = (v); i1 = (n); } \
         else if ((v) > (s2)) { s2 = (v); i2 = (n); } } while (0)

__device__ __forceinline__ void merge2(float& s1, int& i1, float& s2, int& i2,
                                       float t1, int j1, float t2, int j2) {
    if (t1 > s1 || (t1 == s1 && j1 < i1)) {
        float ns2; int ni2;
        if (s1 > t2 || (s1 == t2 && i1 < j2)) { ns2 = s1; ni2 = i1; }
        else                                  { ns2 = t2; ni2 = j2; }
        s1 = t1; i1 = j1; s2 = ns2; i2 = ni2;
    } else if (t1 > s2 || (t1 == s2 && j1 < i2)) {
        s2 = t1; i2 = j1;
    }
}

__global__ void prep_keys_kernel(const float* __restrict__ keys) {
    int i = blockIdx.x * blockDim.x + threadIdx.x;
    if (i < M_KEYS * C_DIM) g_keys_h[i] = __float2half_rn(keys[i]);
}

__global__ __launch_bounds__(THREADS, 2)
void gathering_loss_kernel(const float* __restrict__ q,
                           const float* __restrict__ r,
                           const float* __restrict__ keys,
                           const float* __restrict__ values,
                           float* __restrict__ out)
{
    extern __shared__ char smem[];
    const unsigned sb = smem_u32(smem);
    const int tid  = threadIdx.x;
    const int lane = tid & 31;
    const int wid  = tid >> 5;          // 0..7
    const int rowg = (wid & 3) * 16;    // warp's 16-row group within 64
    const int half = wid >> 2;          // warp's 64-key half of each 128-key chunk
    const int row0 = blockIdx.x * BM;
    const int rot  = (blockIdx.x & 1) * 4;   // phase rotation for co-resident CTAs

    // ---- A tile: q rows -> fp16 smem [m][k], stride 272B ----
    {
        const float4* q4 = (const float4*)(q + (size_t)row0 * C_DIM);
        #pragma unroll
        for (int it = 0; it < (BM * C_DIM / 4) / THREADS; ++it) {
            int i = tid + it * THREADS;
            int m  = i >> 5;
            int k4 = (i & 31) << 2;
            float4 v = q4[i];
            __half2 h01 = __floats2half2_rn(v.x, v.y);
            __half2 h23 = __floats2half2_rn(v.z, v.w);
            char* p = smem + OFF_A + m * SAB + k4 * 2;
            *(__half2*)(p)     = h01;
            *(__half2*)(p + 4) = h23;
        }
    }

    auto load_b = [&](int chunk, int buf) {   // 128 keys = 32 KB
        const char* src = (const char*)(g_keys_h + (size_t)chunk * 128 * C_DIM);
        unsigned dst = sb + OFF_B(buf);
        #pragma unroll
        for (int it = 0; it < 8; ++it) {
            int s  = tid + it * THREADS;      // 2048 16B segments
            int n  = s >> 4;
            int ks = s & 15;
            CP16(dst + n * SAB + ks * 16, src + n * 256 + ks * 16);
        }
    };
    load_b(rot, 0);
    CP_COMMIT();
    __syncthreads();                    // A tile visible (also orders nothing else yet)

    // ---- persistent A fragments (32 regs) ----
    unsigned ahi[8][4];
    {
        int amat = lane >> 3;
        unsigned apart = sb + OFF_A
                       + (unsigned)(rowg + (lane & 7) + ((amat & 1) << 3)) * SAB
                       + ((amat >> 1) << 4);
        #pragma unroll
        for (int ks = 0; ks < 8; ++ks)
            LDSM_X4(ahi[ks][0], ahi[ks][1], ahi[ks][2], ahi[ks][3], apart + ks * 32);
    }

    const int bmat = lane >> 3;
    const unsigned bpart = (unsigned)((lane & 7) + ((bmat >> 1) << 3)) * SAB
                         + ((bmat & 1) << 4)
                         + (unsigned)(half * 64) * SAB;

    float s1a = -3.402823466e38f, s2a = -3.402823466e38f;
    float s1b = -3.402823466e38f, s2b = -3.402823466e38f;
    int i1a = 0, i2a = 0, i1b = 0, i2b = 0;

    #pragma unroll 1
    for (int c = 0; c < 8; ++c) {
        CP_WAIT0();                     // chunk-c data landed in buffer c&1
        __syncthreads();                // ...visible to all; all warps done with buf (c+1)&1
        if (c < 7) {                    // prefetch into the buffer everyone just vacated
            load_b((c + 1 + rot) & 7, (c + 1) & 1);
            CP_COMMIT();
        }

        const unsigned bbuf = sb + OFF_B(c & 1) + bpart;

        float acc[8][4];
        #pragma unroll
        for (int nt = 0; nt < 8; ++nt)
            #pragma unroll
            for (int x = 0; x < 4; ++x) acc[nt][x] = 0.f;

        #pragma unroll
        for (int ks = 0; ks < 8; ++ks) {
            #pragma unroll
            for (int p = 0; p < 4; ++p) {      // pair p covers nt=2p, 2p+1
                unsigned b0, b1, b2, b3;
                LDSM_X4(b0, b1, b2, b3, bbuf + (unsigned)(p * 16) * SAB + ks * 32);
                mma_f16(acc[2 * p],     ahi[ks], b0, b1);
                mma_f16(acc[2 * p + 1], ahi[ks], b2, b3);
            }
        }

        // guarded top-2 update
        const int colbase = ((c + rot) & 7) * 128 + half * 64 + (lane & 3) * 2;
        #pragma unroll
        for (int nt = 0; nt < 8; ++nt) {
            int nb = colbase + nt * 8;
            float mxa = fmaxf(acc[nt][0], acc[nt][1]);
            if (mxa > s2a) {
                UPD(s1a, i1a, s2a, i2a, acc[nt][0], nb);
                UPD(s1a, i1a, s2a, i2a, acc[nt][1], nb + 1);
            }
            float mxb = fmaxf(acc[nt][2], acc[nt][3]);
            if (mxb > s2b) {
                UPD(s1b, i1b, s2b, i2b, acc[nt][2], nb);
                UPD(s1b, i1b, s2b, i2b, acc[nt][3], nb + 1);
            }
        }
    }
    __syncthreads();                    // all compute done before smem reuse

    // ---- quad merge -> (row, half) top-2 ----
    #pragma unroll
    for (int off = 1; off <= 2; off <<= 1) {
        float t1 = __shfl_xor_sync(0xffffffffu, s1a, off);
        int   j1 = __shfl_xor_sync(0xffffffffu, i1a, off);
        float t2 = __shfl_xor_sync(0xffffffffu, s2a, off);
        int   j2 = __shfl_xor_sync(0xffffffffu, i2a, off);
        merge2(s1a, i1a, s2a, i2a, t1, j1, t2, j2);
        t1 = __shfl_xor_sync(0xffffffffu, s1b, off);
        j1 = __shfl_xor_sync(0xffffffffu, i1b, off);
        t2 = __shfl_xor_sync(0xffffffffu, s2b, off);
        j2 = __shfl_xor_sync(0xffffffffu, i2b, off);
        merge2(s1b, i1b, s2b, i2b, t1, j1, t2, j2);
    }

    // cand smem: approx (score, idx) 4 per row
    float* cs = (float*)smem;
    int*   ci = (int*)(smem + 1024);
    if ((lane & 3) == 0) {
        int ra = rowg + (lane >> 2);
        cs[ra * 4 + half * 2 + 0] = s1a;  ci[ra * 4 + half * 2 + 0] = i1a;
        cs[ra * 4 + half * 2 + 1] = s2a;  ci[ra * 4 + half * 2 + 1] = i2a;
        cs[(ra + 8) * 4 + half * 2 + 0] = s1b;  ci[(ra + 8) * 4 + half * 2 + 0] = i1b;
        cs[(ra + 8) * 4 + half * 2 + 1] = s2b;  ci[(ra + 8) * 4 + half * 2 + 1] = i2b;
    }
    __syncthreads();

    // ---- epilogue: 4 threads/row; approx top-2 -> exact rescore -> losses ----
    {
        int row = tid >> 2;              // 0..63
        int sub = tid & 3;
        int grow = row0 + row;
        float4 sc4 = *(const float4*)&cs[row * 4];
        int4   id4 = *(const int4*)&ci[row * 4];
        float sc[4] = {sc4.x, sc4.y, sc4.z, sc4.w};
        int   id[4] = {id4.x, id4.y, id4.z, id4.w};

        int b0 = 0;
        #pragma unroll
        for (int j = 1; j < 4; ++j)
            if (sc[j] > sc[b0] || (sc[j] == sc[b0] && id[j] < id[b0])) b0 = j;
        int b1 = (b0 == 0) ? 1 : 0;
        #pragma unroll
        for (int j = 0; j < 4; ++j)
            if (j != b0 && (sc[j] > sc[b1] || (sc[j] == sc[b1] && id[j] < id[b1]))) b1 = j;
        int c1 = id[b0], c2 = id[b1];

        const float4* qp = (const float4*)(q + (size_t)grow * C_DIM + sub * 32);
        float4 qv[8];
        #pragma unroll
        for (int i = 0; i < 8; ++i) qv[i] = qp[i];

        const float4* ka = (const float4*)(keys + (size_t)c1 * C_DIM + sub * 32);
        const float4* kb = (const float4*)(keys + (size_t)c2 * C_DIM + sub * 32);
        float sa = 0.f, sc2 = 0.f;
        #pragma unroll
        for (int i = 0; i < 8; ++i) {
            float4 a = qv[i], x = ka[i], y = kb[i];
            sa  = fmaf(a.x, x.x, sa);  sa  = fmaf(a.y, x.y, sa);
            sa  = fmaf(a.z, x.z, sa);  sa  = fmaf(a.w, x.w, sa);
            sc2 = fmaf(a.x, y.x, sc2); sc2 = fmaf(a.y, y.y, sc2);
            sc2 = fmaf(a.z, y.z, sc2); sc2 = fmaf(a.w, y.w, sc2);
        }
        #pragma unroll
        for (int off = 1; off <= 2; off <<= 1) {
            sa  += __shfl_xor_sync(0xffffffffu, sa,  off);
            sc2 += __shfl_xor_sync(0xffffffffu, sc2, off);
        }
        int bi = (sc2 > sa || (sc2 == sa && c2 < c1)) ? c2 : c1;

        const float4* kp = (const float4*)(keys   + (size_t)bi   * C_DIM + sub * 32);
        const float4* rp = (const float4*)(r      + (size_t)grow * C_DIM + sub * 32);
        const float4* vp = (const float4*)(values + (size_t)bi   * C_DIM + sub * 32);
        float sk = 0.f, sv = 0.f;
        #pragma unroll
        for (int i = 0; i < 8; ++i) {
            float4 a = qv[i], b = kp[i];
            float d;
            d = a.x - b.x; sk = fmaf(d, d, sk);
            d = a.y - b.y; sk = fmaf(d, d, sk);
            d = a.z - b.z; sk = fmaf(d, d, sk);
            d = a.w - b.w; sk = fmaf(d, d, sk);
            float4 e = rp[i], f = vp[i];
            d = e.x - f.x; sv = fmaf(d, d, sv);
            d = e.y - f.y; sv = fmaf(d, d, sv);
            d = e.z - f.z; sv = fmaf(d, d, sv);
            d = e.w - f.w; sv = fmaf(d, d, sv);
        }
        #pragma unroll
        for (int off = 1; off <= 2; off <<= 1) {
            sk += __shfl_xor_sync(0xffffffffu, sk, off);
            sv += __shfl_xor_sync(0xffffffffu, sv, off);
        }
        if (sub == 0) out[grow]           = sk;
        if (sub == 1) out[T_TOTAL + grow] = sv;
    }
}

extern "C" void kernel_launch(void* const* d_in, const int* in_sizes, int n_in,
                              void* d_out, int out_size)
{
    const float* q      = (const float*)d_in[0];
    const float* r      = (const float*)d_in[1];
    const float* keys   = (const float*)d_in[2];
    const float* values = (const float*)d_in[3];
    float* out = (float*)d_out;

    prep_keys_kernel<<<(M_KEYS * C_DIM + 255) / 256, 256>>>(keys);

    cudaFuncSetAttribute(gathering_loss_kernel,
                         cudaFuncAttributeMaxDynamicSharedMemorySize, SM_TOTAL);
    gathering_loss_kernel<<<T_TOTAL / BM, THREADS, SM_TOTAL>>>(q, r, keys, values, out);
}